// round 14
// baseline (speedup 1.0000x reference)
#include <cuda_runtime.h>

#define W56   56
#define HW    3136
#define WC_N  32
#define C_N   256
#define GRP   8
#define LW    16     // lanes per image row (14 active + 2 idle)
#define RPB   14     // rows per block
#define NTHR  (LW * RPB)   // 224

__device__ __forceinline__ float4 zf4() { return make_float4(0.f, 0.f, 0.f, 0.f); }

__device__ __forceinline__ float getc(const float4& v, int i) {
    switch (i) { case 0: return v.x; case 1: return v.y; case 2: return v.z; default: return v.w; }
}
__device__ __forceinline__ void addc(float4& v, int i, float a) {
    switch (i) { case 0: v.x += a; break; case 1: v.y += a; break;
                 case 2: v.z += a; break; default: v.w += a; break; }
}

// Logical 12-float window [w4-4, w4+8) around this lane's M = x[row, w4..w4+4).
// Halo words come from neighbor lanes via shfl (2*D per stream).
template<int D>
struct Win {
    float4 M;
    float  Lc[4];   // Lc[k] = pixel w4 - D + k   (k = 0..D-1)
    float  Rc[4];   // Rc[k] = pixel w4 + 4 + k   (k = 0..D-1)
};

template<int D>
__device__ __forceinline__ Win<D> make_win(float4 M, bool lv, bool rvx) {
    Win<D> w; w.M = M;
#pragma unroll
    for (int k = 0; k < D; k++) {
        float l = __shfl_up_sync  (0xffffffffu, getc(M, 4 - D + k), 1, LW);
        float r = __shfl_down_sync(0xffffffffu, getc(M, k),         1, LW);
        w.Lc[k] = lv  ? l : 0.f;
        w.Rc[k] = rvx ? r : 0.f;
    }
    return w;
}

template<int D>
__device__ __forceinline__ float wat(const Win<D>& w, int I) {   // I compile-time const
    if (I < 4)      return w.Lc[I - (4 - D)];
    else if (I < 8) return getc(w.M, I - 4);
    else            return w.Rc[I - 8];
}

template<int D>
__device__ __forceinline__ void fma4(float4& acc, const float4& wk, const Win<D>& a, int c) {
#pragma unroll
    for (int i = 0; i < 4; i++)
        addc(acc, i, getc(wk, i) * wat<D>(a, 4 + i + c));
}

template<int D>
__device__ __forceinline__ void lcd_body(const float* __restrict__ x,
                                         const float* __restrict__ weight,
                                         float* __restrict__ out,
                                         int b, int wc, int h, int w4, bool active)
{
    const bool lv = (w4 > 0), rvx = (w4 < 52);
    bool rv[3];
    int  roff[3];
#pragma unroll
    for (int j = 0; j < 3; j++) {
        const int hh = h + (j - 1) * D;
        rv[j]   = ((unsigned)hh < (unsigned)W56) && active;
        roff[j] = hh * W56 + w4;
    }

    // weight base for this pixel; re-read per g-pair (L1-resident: 28KB/block)
    const float* wp = weight + ((size_t)(b * WC_N + wc) * 9) * HW + h * W56 + w4;
    const float* xb = x   + (size_t)(b * C_N + wc) * HW;
    float*       ob = out + (size_t)(b * C_N + wc) * HW + h * W56 + w4;

#pragma unroll 1
    for (int g = 0; g < GRP; g += 2) {
        const float* xp0 = xb + (size_t)g * WC_N * HW;
        const float* xp1 = xp0 + (size_t)WC_N * HW;
        float4 acc0 = zf4(), acc1 = zf4();
#pragma unroll
        for (int j = 0; j < 3; j++) {
            // 5 independent LDG.128: 3 weights (L1-hot) + 2 x rows
            float4 wk0 = active ? *(const float4*)(wp + (j * 3 + 0) * HW) : zf4();
            float4 wk1 = active ? *(const float4*)(wp + (j * 3 + 1) * HW) : zf4();
            float4 wk2 = active ? *(const float4*)(wp + (j * 3 + 2) * HW) : zf4();
            float4 m0  = rv[j] ? *(const float4*)(xp0 + roff[j]) : zf4();
            float4 m1  = rv[j] ? *(const float4*)(xp1 + roff[j]) : zf4();

            Win<D> a0 = make_win<D>(m0, lv, rvx);
            Win<D> a1 = make_win<D>(m1, lv, rvx);

            fma4<D>(acc0, wk0, a0, -D);
            fma4<D>(acc0, wk1, a0,  0);
            fma4<D>(acc0, wk2, a0,  D);
            fma4<D>(acc1, wk0, a1, -D);
            fma4<D>(acc1, wk1, a1,  0);
            fma4<D>(acc1, wk2, a1,  D);
        }
        if (active) {
            *(float4*)(ob + (size_t)g * WC_N * HW)       = acc0;
            *(float4*)(ob + (size_t)(g + 1) * WC_N * HW) = acc1;
        }
    }
}

__global__ __launch_bounds__(NTHR)
void lcd_kernel(const float* __restrict__ x,
                const float* __restrict__ weight,
                const int*   __restrict__ dilation,
                float*       __restrict__ out)
{
    const int tx = threadIdx.x;            // 0..15 (lane within row)
    const int ty = threadIdx.y;            // 0..13 (row within strip)
    const int wc = blockIdx.y;
    const int b  = blockIdx.z;
    const int h  = blockIdx.x * RPB + ty;  // 0..55
    const int w4 = tx * 4;
    const bool active = (tx < 14);

    const int d = __ldg(&dilation[wc]);    // 1..4, uniform per block -> no divergence

    switch (d) {
        case 1:  lcd_body<1>(x, weight, out, b, wc, h, w4, active); break;
        case 2:  lcd_body<2>(x, weight, out, b, wc, h, w4, active); break;
        case 3:  lcd_body<3>(x, weight, out, b, wc, h, w4, active); break;
        default: lcd_body<4>(x, weight, out, b, wc, h, w4, active); break;
    }
}

extern "C" void kernel_launch(void* const* d_in, const int* in_sizes, int n_in,
                              void* d_out, int out_size)
{
    const float* x        = (const float*)d_in[0];
    const float* weight   = (const float*)d_in[1];
    const int*   dilation = (const int*)d_in[2];
    float*       out      = (float*)d_out;

    dim3 grid(W56 / RPB, WC_N, 8);   // (4, 32, 8)
    dim3 block(LW, RPB);             // 224 threads
    lcd_kernel<<<grid, block>>>(x, weight, dilation, out);
}

// round 15
// speedup vs baseline: 1.2561x; 1.2561x over previous
#include <cuda_runtime.h>

#define W56   56
#define HW    3136
#define WC_N  32
#define C_N   256
#define GRP   8
#define LW    16     // lanes per image row (14 active + 2 idle)
#define RPB   14     // rows per block
#define NTHR  (LW * RPB)   // 224

__device__ __forceinline__ float4 zf4() { return make_float4(0.f, 0.f, 0.f, 0.f); }

__device__ __forceinline__ float getc(const float4& v, int i) {
    switch (i) { case 0: return v.x; case 1: return v.y; case 2: return v.z; default: return v.w; }
}
__device__ __forceinline__ void addc(float4& v, int i, float a) {
    switch (i) { case 0: v.x += a; break; case 1: v.y += a; break;
                 case 2: v.z += a; break; default: v.w += a; break; }
}

// Logical 12-float window [w4-4, w4+8) around this lane's M = x[row, w4..w4+4).
// Halo words come from neighbor lanes via shfl (2*D per stream).
template<int D>
struct Win {
    float4 M;
    float  Lc[4];   // Lc[k] = pixel w4 - D + k   (k = 0..D-1)
    float  Rc[4];   // Rc[k] = pixel w4 + 4 + k   (k = 0..D-1)
};

template<int D>
__device__ __forceinline__ Win<D> make_win(float4 M, bool lv, bool rvx) {
    Win<D> w; w.M = M;
#pragma unroll
    for (int k = 0; k < D; k++) {
        float l = __shfl_up_sync  (0xffffffffu, getc(M, 4 - D + k), 1, LW);
        float r = __shfl_down_sync(0xffffffffu, getc(M, k),         1, LW);
        w.Lc[k] = lv  ? l : 0.f;
        w.Rc[k] = rvx ? r : 0.f;
    }
    return w;
}

template<int D>
__device__ __forceinline__ float wat(const Win<D>& w, int I) {   // I compile-time const
    if (I < 4)      return w.Lc[I - (4 - D)];
    else if (I < 8) return getc(w.M, I - 4);
    else            return w.Rc[I - 8];
}

template<int D>
__device__ __forceinline__ void fma4(float4& acc, const float4& wk, const Win<D>& a, int c) {
#pragma unroll
    for (int i = 0; i < 4; i++)
        addc(acc, i, getc(wk, i) * wat<D>(a, 4 + i + c));
}

template<int D>
__device__ __forceinline__ void lcd_body(const float* __restrict__ x,
                                         const float* __restrict__ weight,
                                         float* __restrict__ out,
                                         int b, int wc, int h, int w4, bool active)
{
    // 9 taps x 4 pixels of weights in registers, reused across all 8 channel groups.
    // Streaming read (evict-first): weights have zero reuse; keep them out of L1
    // so the x rows (3x vertical reuse across ty-threads) stay resident.
    float4 wg[9];
    if (active) {
        const float4* wp = (const float4*)(weight + ((size_t)(b * WC_N + wc) * 9) * HW + h * W56 + w4);
#pragma unroll
        for (int k = 0; k < 9; k++) wg[k] = __ldcs(wp + k * (HW / 4));
    } else {
#pragma unroll
        for (int k = 0; k < 9; k++) wg[k] = zf4();
    }

    const bool lv = (w4 > 0), rvx = (w4 < 52);
    bool rv[3];
    int  roff[3];
#pragma unroll
    for (int j = 0; j < 3; j++) {
        const int hh = h + (j - 1) * D;
        rv[j]   = ((unsigned)hh < (unsigned)W56) && active;
        roff[j] = (hh * W56 + w4) / 4;   // float4 index
    }

    const float4* xb = (const float4*)(x + (size_t)(b * C_N + wc) * HW);
    float*        ob = out + (size_t)(b * C_N + wc) * HW + h * W56 + w4;

#pragma unroll 1
    for (int g = 0; g < GRP; g += 2) {
        const float4* xp0 = xb + (size_t)g * WC_N * (HW / 4);
        const float4* xp1 = xp0 + (size_t)WC_N * (HW / 4);
        float4 acc0 = zf4(), acc1 = zf4();

        // front-batch 6 independent LDG.128 (both g-streams, 3 tap rows); default
        // caching: x is the only tensor with L1 temporal reuse
        float4 M0[3], M1[3];
#pragma unroll
        for (int j = 0; j < 3; j++) {
            M0[j] = rv[j] ? __ldg(xp0 + roff[j]) : zf4();
            M1[j] = rv[j] ? __ldg(xp1 + roff[j]) : zf4();
        }
#pragma unroll
        for (int j = 0; j < 3; j++) {
            Win<D> a0 = make_win<D>(M0[j], lv, rvx);
            Win<D> a1 = make_win<D>(M1[j], lv, rvx);
#pragma unroll
            for (int kw = 0; kw < 3; kw++) {
                const int c = (kw - 1) * D;
                fma4<D>(acc0, wg[j * 3 + kw], a0, c);
                fma4<D>(acc1, wg[j * 3 + kw], a1, c);
            }
        }
        if (active) {
            __stcs((float4*)(ob + (size_t)g * WC_N * HW),       acc0);
            __stcs((float4*)(ob + (size_t)(g + 1) * WC_N * HW), acc1);
        }
    }
}

__global__ __launch_bounds__(NTHR)
void lcd_kernel(const float* __restrict__ x,
                const float* __restrict__ weight,
                const int*   __restrict__ dilation,
                float*       __restrict__ out)
{
    const int tx = threadIdx.x;            // 0..15 (lane within row)
    const int ty = threadIdx.y;            // 0..13 (row within strip)
    const int wc = blockIdx.y;
    const int b  = blockIdx.z;
    const int h  = blockIdx.x * RPB + ty;  // 0..55
    const int w4 = tx * 4;
    const bool active = (tx < 14);

    const int d = __ldg(&dilation[wc]);    // 1..4, uniform per block -> no divergence

    switch (d) {
        case 1:  lcd_body<1>(x, weight, out, b, wc, h, w4, active); break;
        case 2:  lcd_body<2>(x, weight, out, b, wc, h, w4, active); break;
        case 3:  lcd_body<3>(x, weight, out, b, wc, h, w4, active); break;
        default: lcd_body<4>(x, weight, out, b, wc, h, w4, active); break;
    }
}

extern "C" void kernel_launch(void* const* d_in, const int* in_sizes, int n_in,
                              void* d_out, int out_size)
{
    const float* x        = (const float*)d_in[0];
    const float* weight   = (const float*)d_in[1];
    const int*   dilation = (const int*)d_in[2];
    float*       out      = (float*)d_out;

    dim3 grid(W56 / RPB, WC_N, 8);   // (4, 32, 8)
    dim3 block(LW, RPB);             // 224 threads
    lcd_kernel<<<grid, block>>>(x, weight, dilation, out);
}